// round 1
// baseline (speedup 1.0000x reference)
#include <cuda_runtime.h>
#include <cuda_bf16.h>

// SpatialBlock: x[16,256,128,128] fp32
//   max_c(x), mean_c(x) -> [B,2,H,W] -> conv7x7 (2->1, SAME, zero pad) + bias
//   gate = hsigmoid(.) ; out = x * gate
//
// Kernel 1: channel reduction (max & mean) -> device scratch (2 MB)
// Kernel 2: conv + hsigmoid + broadcast multiply

#define Bn 16
#define Cn 256
#define Hn 128
#define Wn 128
#define HWn (Hn * Wn)

// Scratch (static device globals -- no allocation in kernel_launch)
__device__ float g_max[Bn * HWn];
__device__ float g_avg[Bn * HWn];

__global__ void __launch_bounds__(256)
reduce_kernel(const float* __restrict__ x) {
    // Each thread handles 4 consecutive pixels (one float4) of one (b, HW) plane.
    int t = blockIdx.x * 256 + threadIdx.x;       // 0 .. B*HW/4 - 1
    int b = t / (HWn / 4);
    int p4 = t - b * (HWn / 4);                    // float4 index within plane

    const float4* xb = reinterpret_cast<const float4*>(x) +
                       (size_t)b * Cn * (HWn / 4) + p4;

    float4 v = xb[0];
    float4 mx = v;
    float4 sm = v;

#pragma unroll 8
    for (int c = 1; c < Cn; c++) {
        float4 u = xb[(size_t)c * (HWn / 4)];
        mx.x = fmaxf(mx.x, u.x); mx.y = fmaxf(mx.y, u.y);
        mx.z = fmaxf(mx.z, u.z); mx.w = fmaxf(mx.w, u.w);
        sm.x += u.x; sm.y += u.y; sm.z += u.z; sm.w += u.w;
    }

    const float inv = 1.0f / (float)Cn;
    sm.x *= inv; sm.y *= inv; sm.z *= inv; sm.w *= inv;

    reinterpret_cast<float4*>(g_max)[(size_t)b * (HWn / 4) + p4] = mx;
    reinterpret_cast<float4*>(g_avg)[(size_t)b * (HWn / 4) + p4] = sm;
}

#define TW 32   // tile width  (pixels)
#define TH 16   // tile height (pixels)
// block = (8,16) = 128 threads, each thread owns 4 consecutive-w pixels (float4)

__global__ void __launch_bounds__(128)
gate_mul_kernel(const float* __restrict__ x,
                const float* __restrict__ cw,   // [1,2,7,7] = 98 floats
                const float* __restrict__ cb,   // [1]
                float* __restrict__ out) {
    __shared__ float sw[98];
    __shared__ float sbias;
    __shared__ float smax[TH + 6][TW + 6];
    __shared__ float savg[TH + 6][TW + 6];

    int tid = threadIdx.y * 8 + threadIdx.x;    // 0..127
    if (tid < 98) sw[tid] = cw[tid];
    if (tid == 98) sbias = cb[0];

    int b  = blockIdx.z;
    int h0 = blockIdx.y * TH;
    int w0 = blockIdx.x * TW;

    const float* bmax = g_max + b * HWn;
    const float* bavg = g_avg + b * HWn;

    // Cooperative halo load (zero padding == conv SAME zero-pad)
    for (int i = tid; i < (TH + 6) * (TW + 6); i += 128) {
        int r  = i / (TW + 6);
        int cc = i - r * (TW + 6);
        int hh = h0 + r - 3;
        int ww = w0 + cc - 3;
        float vm = 0.0f, va = 0.0f;
        if ((unsigned)hh < (unsigned)Hn && (unsigned)ww < (unsigned)Wn) {
            int gi = hh * Wn + ww;
            vm = bmax[gi];
            va = bavg[gi];
        }
        smax[r][cc] = vm;
        savg[r][cc] = va;
    }
    __syncthreads();

    int tx4 = threadIdx.x * 4;   // 0,4,...,28
    int ty  = threadIdx.y;       // 0..15

    float4 acc = make_float4(sbias, sbias, sbias, sbias);
#pragma unroll
    for (int ky = 0; ky < 7; ky++) {
#pragma unroll
        for (int kx = 0; kx < 7; kx++) {
            float wm = sw[ky * 7 + kx];
            float wa = sw[49 + ky * 7 + kx];
            acc.x += wm * smax[ty + ky][tx4 + 0 + kx] + wa * savg[ty + ky][tx4 + 0 + kx];
            acc.y += wm * smax[ty + ky][tx4 + 1 + kx] + wa * savg[ty + ky][tx4 + 1 + kx];
            acc.z += wm * smax[ty + ky][tx4 + 2 + kx] + wa * savg[ty + ky][tx4 + 2 + kx];
            acc.w += wm * smax[ty + ky][tx4 + 3 + kx] + wa * savg[ty + ky][tx4 + 3 + kx];
        }
    }

    // hsigmoid: clip(v+3, 0, 6)/6 == saturate((v+3)/6)
    const float s = 1.0f / 6.0f;
    float4 g;
    g.x = __saturatef((acc.x + 3.0f) * s);
    g.y = __saturatef((acc.y + 3.0f) * s);
    g.z = __saturatef((acc.z + 3.0f) * s);
    g.w = __saturatef((acc.w + 3.0f) * s);

    int prow4 = ((h0 + ty) * Wn + w0 + tx4) >> 2;   // float4 index in plane
    const float4* xin  = reinterpret_cast<const float4*>(x)   + (size_t)b * Cn * (HWn / 4) + prow4;
    float4*       xout = reinterpret_cast<float4*>(out)       + (size_t)b * Cn * (HWn / 4) + prow4;

#pragma unroll 4
    for (int c = 0; c < Cn; c++) {
        float4 v = xin[(size_t)c * (HWn / 4)];
        v.x *= g.x; v.y *= g.y; v.z *= g.z; v.w *= g.w;
        xout[(size_t)c * (HWn / 4)] = v;
    }
}

extern "C" void kernel_launch(void* const* d_in, const int* in_sizes, int n_in,
                              void* d_out, int out_size) {
    const float* x  = (const float*)d_in[0];
    const float* cw = (const float*)d_in[1];
    const float* cb = (const float*)d_in[2];
    float* out = (float*)d_out;

    // Kernel 1: 16*16384/4 threads / 256 = 256 blocks
    reduce_kernel<<<(Bn * HWn / 4) / 256, 256>>>(x);

    // Kernel 2: grid (W/TW, H/TH, B) = (4, 8, 16) = 512 blocks of 128 threads
    gate_mul_kernel<<<dim3(Wn / TW, Hn / TH, Bn), dim3(8, 16)>>>(x, cw, cb, out);
}

// round 3
// speedup vs baseline: 1.0362x; 1.0362x over previous
#include <cuda_runtime.h>
#include <cuda_bf16.h>

// SpatialBlock: x[16,256,128,128] fp32
//   max_c(x), mean_c(x) -> conv7x7 (2->1, SAME zero pad) + bias -> hsigmoid -> x * gate
//
// K1: channel max+mean -> device scratch (2 MB), 512 blocks x 128 thr, unroll 16
// K2: conv+hsigmoid gate in smem, then channel-split broadcast multiply,
//     256 thr/block (2 channel-halves x 128 px4), unroll 8
// R2 fix: __align__(16) on shared arrays (LDS.128 from sgate trapped on
//         misaligned base -- shared float arrays are only 4B-aligned).

#define Bn 16
#define Cn 256
#define Hn 128
#define Wn 128
#define HWn (Hn * Wn)

__device__ float g_max[Bn * HWn];
__device__ float g_avg[Bn * HWn];

__global__ void __launch_bounds__(128)
reduce_kernel(const float* __restrict__ x) {
    int t = blockIdx.x * 128 + threadIdx.x;       // 0 .. B*HW/4 - 1
    int b = t / (HWn / 4);
    int p4 = t - b * (HWn / 4);

    const float4* xb = reinterpret_cast<const float4*>(x) +
                       (size_t)b * Cn * (HWn / 4) + p4;

    float4 v = xb[0];
    float4 mx = v;
    float4 sm = v;

#pragma unroll 16
    for (int c = 1; c < Cn; c++) {
        float4 u = xb[(size_t)c * (HWn / 4)];
        mx.x = fmaxf(mx.x, u.x); mx.y = fmaxf(mx.y, u.y);
        mx.z = fmaxf(mx.z, u.z); mx.w = fmaxf(mx.w, u.w);
        sm.x += u.x; sm.y += u.y; sm.z += u.z; sm.w += u.w;
    }

    const float inv = 1.0f / (float)Cn;
    sm.x *= inv; sm.y *= inv; sm.z *= inv; sm.w *= inv;

    reinterpret_cast<float4*>(g_max)[(size_t)b * (HWn / 4) + p4] = mx;
    reinterpret_cast<float4*>(g_avg)[(size_t)b * (HWn / 4) + p4] = sm;
}

#define TW 32   // tile width  (pixels)
#define TH 16   // tile height (pixels)

__global__ void __launch_bounds__(256)
gate_mul_kernel(const float* __restrict__ x,
                const float* __restrict__ cw,   // [1,2,7,7] = 98 floats
                const float* __restrict__ cb,   // [1]
                float* __restrict__ out) {
    __shared__ float sw[98];
    __shared__ float sbias;
    __shared__ __align__(16) float smax[TH + 6][TW + 6];
    __shared__ __align__(16) float savg[TH + 6][TW + 6];
    __shared__ __align__(16) float sgate[TH][TW];

    int tid = threadIdx.x;                        // 0..255
    if (tid < 98) sw[tid] = cw[tid];
    if (tid == 98) sbias = cb[0];

    int b  = blockIdx.z;
    int h0 = blockIdx.y * TH;
    int w0 = blockIdx.x * TW;

    const float* bmax = g_max + b * HWn;
    const float* bavg = g_avg + b * HWn;

    // Cooperative halo load (zero padding == conv SAME zero-pad)
    for (int i = tid; i < (TH + 6) * (TW + 6); i += 256) {
        int r  = i / (TW + 6);
        int cc = i - r * (TW + 6);
        int hh = h0 + r - 3;
        int ww = w0 + cc - 3;
        float vm = 0.0f, va = 0.0f;
        if ((unsigned)hh < (unsigned)Hn && (unsigned)ww < (unsigned)Wn) {
            int gi = hh * Wn + ww;
            vm = bmax[gi];
            va = bavg[gi];
        }
        smax[r][cc] = vm;
        savg[r][cc] = va;
    }
    __syncthreads();

    // Conv + hsigmoid: each thread computes 2 adjacent pixels of the 32x16 tile
    {
        int p  = tid * 2;          // 0..510
        int r  = p >> 5;           // tile row 0..15
        int cp = p & 31;           // tile col (even)
        float a0 = sbias, a1 = sbias;
#pragma unroll
        for (int ky = 0; ky < 7; ky++) {
#pragma unroll
            for (int kx = 0; kx < 7; kx++) {
                float wm = sw[ky * 7 + kx];
                float wa = sw[49 + ky * 7 + kx];
                a0 += wm * smax[r + ky][cp + 0 + kx] + wa * savg[r + ky][cp + 0 + kx];
                a1 += wm * smax[r + ky][cp + 1 + kx] + wa * savg[r + ky][cp + 1 + kx];
            }
        }
        const float s = 1.0f / 6.0f;
        sgate[r][cp + 0] = __saturatef((a0 + 3.0f) * s);
        sgate[r][cp + 1] = __saturatef((a1 + 3.0f) * s);
    }
    __syncthreads();

    // Broadcast multiply: thread = (channel-half, px4). Each thread streams
    // 128 channels of one float4 pixel. 256 threads cover 2 halves x 128 px4.
    int px4   = tid & 127;         // 0..127  (float4 pixel within tile)
    int chalf = tid >> 7;          // 0 or 1
    int rr  = px4 >> 3;            // tile row
    int cc4 = px4 & 7;             // float4 col within tile row

    float4 g = *reinterpret_cast<const float4*>(&sgate[rr][cc4 * 4]);

    const size_t plane4 = HWn / 4;
    int prow4 = ((h0 + rr) * Wn + w0 + cc4 * 4) >> 2;
    const float4* xin = reinterpret_cast<const float4*>(x) +
                        (size_t)b * Cn * plane4 + (size_t)chalf * 128 * plane4 + prow4;
    float4* xout = reinterpret_cast<float4*>(out) +
                   (size_t)b * Cn * plane4 + (size_t)chalf * 128 * plane4 + prow4;

#pragma unroll 8
    for (int c = 0; c < 128; c++) {
        float4 v = xin[(size_t)c * plane4];
        v.x *= g.x; v.y *= g.y; v.z *= g.z; v.w *= g.w;
        xout[(size_t)c * plane4] = v;
    }
}

extern "C" void kernel_launch(void* const* d_in, const int* in_sizes, int n_in,
                              void* d_out, int out_size) {
    const float* x  = (const float*)d_in[0];
    const float* cw = (const float*)d_in[1];
    const float* cb = (const float*)d_in[2];
    float* out = (float*)d_out;

    reduce_kernel<<<(Bn * HWn / 4) / 128, 128>>>(x);

    gate_mul_kernel<<<dim3(Wn / TW, Hn / TH, Bn), 256>>>(x, cw, cb, out);
}